// round 7
// baseline (speedup 1.0000x reference)
#include <cuda_runtime.h>

// Problem dims (fixed by reference setup_inputs)
#define B_DIM 8192
#define T_DIM 2048
#define H     20
#define CTA_ROWS 64       // batch rows per CTA
#define NTHR  320         // 10 warps; warp w = unit-pair w; lane carries 2 rows

typedef unsigned long long u64;

// Scratch (allocation-free rule: __device__ globals)
__device__ float g_xT[(size_t)T_DIM * B_DIM];   // x transposed: [t][b]
__device__ float g_outT[(size_t)T_DIM * B_DIM]; // out transposed: [t][b]
__device__ u64   g_wpack[H * 40];               // staging for constant copy

// Recurrent weights in CONSTANT memory: dedicated const-cache port,
// zero smem-crossbar traffic. c_WP[u*40 + p*4 + g] =
// (W_hh[g*H+2p][u], W_hh[g*H+2p+1][u])  — dest-unit-pair packed.
__constant__ u64 c_WP[H * 40];

// ---------------- f32x2 helpers ----------------
__device__ __forceinline__ u64 pk(float lo, float hi) {
    u64 r; asm("mov.b64 %0,{%1,%2};" : "=l"(r) : "f"(lo), "f"(hi)); return r;
}
__device__ __forceinline__ void upk(u64 v, float& lo, float& hi) {
    asm("mov.b64 {%0,%1},%2;" : "=f"(lo), "=f"(hi) : "l"(v));
}
__device__ __forceinline__ u64 fma2(u64 a, u64 b, u64 c) {
    u64 d; asm("fma.rn.f32x2 %0,%1,%2,%3;" : "=l"(d) : "l"(a), "l"(b), "l"(c)); return d;
}
__device__ __forceinline__ float tanh_a(float x) {
    float r; asm("tanh.approx.f32 %0,%1;" : "=f"(r) : "f"(x)); return r;
}

// LSTM cell via MUFU.TANH: 5 MUFU + ~9 FMA-pipe ops.
// sigmoid(x) = 0.5*tanh(0.5x) + 0.5
__device__ __forceinline__ void cell(float ig, float fg, float gg, float og,
                                     float& c, float& h) {
    float si = fmaf(0.5f, tanh_a(0.5f * ig), 0.5f);
    float sf = fmaf(0.5f, tanh_a(0.5f * fg), 0.5f);
    float so = fmaf(0.5f, tanh_a(0.5f * og), 0.5f);
    float tg = tanh_a(gg);
    float cn = sf * c + si * tg;
    float tc = tanh_a(cn);
    c = cn;
    h = so * tc;
}

// ---------------- weight packer (runs once per launch) ----------------
__global__ void pack_weights(const float* __restrict__ W_hh) {
    int i = blockIdx.x * 256 + threadIdx.x;
    if (i < H * 40) {
        int u = i / 40, j = i % 40;
        int p = j >> 2, g = j & 3;                   // dest unit-pair p, gate g
        float wa = W_hh[(g * H + 2 * p    ) * H + u];
        float wb = W_hh[(g * H + 2 * p + 1) * H + u];
        g_wpack[i] = pk(wa, wb);
    }
}

// ---------------- transposes ----------------
__global__ void transpose_in(const float* __restrict__ in) {
    __shared__ float tile[32][33];
    int c0 = blockIdx.x * 32, r0 = blockIdx.y * 32;
    int tx = threadIdx.x, ty = threadIdx.y;
#pragma unroll
    for (int i = 0; i < 32; i += 8)
        tile[ty + i][tx] = in[(size_t)(r0 + ty + i) * T_DIM + c0 + tx];
    __syncthreads();
#pragma unroll
    for (int i = 0; i < 32; i += 8)
        g_xT[(size_t)(c0 + ty + i) * B_DIM + r0 + tx] = tile[tx][ty + i];
}

__global__ void transpose_out(float* __restrict__ out) {
    __shared__ float tile[32][33];
    int c0 = blockIdx.x * 32, r0 = blockIdx.y * 32;
    int tx = threadIdx.x, ty = threadIdx.y;
#pragma unroll
    for (int i = 0; i < 32; i += 8)
        tile[ty + i][tx] = g_outT[(size_t)(r0 + ty + i) * B_DIM + c0 + tx];
    __syncthreads();
#pragma unroll
    for (int i = 0; i < 32; i += 8)
        out[(size_t)(c0 + ty + i) * T_DIM + r0 + tx] = tile[tx][ty + i];
}

// ---------------- main persistent LSTM kernel ----------------
// 128 CTAs x 320 threads (10 warps). CTA owns 64 batch rows.
// Warp up owns UNIT PAIR {2up, 2up+1}. Lane owns rows {2*lane, 2*lane+1}.
// Weights stream from __constant__ (const port); h goes through smem as
// float4 [pair][row][unit-in-pair] so each warp does 10 LDS.128 + 1 STS.128.
// One __syncthreads per timestep (double-buffered h).
__global__ __launch_bounds__(NTHR, 1) void lstm_kernel(
    const float* __restrict__ W1, const float* __restrict__ b1,
    const float* __restrict__ W_ih, const float* __restrict__ W_hh,
    const float* __restrict__ b_ih, const float* __restrict__ b_hh,
    const float* __restrict__ W2, const float* __restrict__ b2)
{
    __shared__ __align__(16) u64 uvz[80];            // [p*8+2g]=u-pair, [+1]=v-pair
    __shared__ u64 w2q[10];                          // (W2[2p], W2[2p+1])
    __shared__ float b2_s;
    // h as [buf][pair][row][unit-in-pair]; lane's 16B = both rows x both units
    __shared__ __align__(16) float h_s[2][10][CTA_ROWS][2];

    const int tid  = threadIdx.x;
    const int lane = tid & 31;
    const int up   = tid >> 5;                       // unit pair index 0..9
    const int up4  = up * 4;
    const int rowbase = blockIdx.x * CTA_ROWS;
    const int rA = 2 * lane;                         // rows owned by this lane

    // --- one-time setup ---
    if (tid < 40) {
        int p = tid >> 2, g = tid & 3;
        float su[2], sv[2];
#pragma unroll
        for (int s = 0; s < 2; ++s) {
            int k = g * H + 2 * p + s;               // original gate-row index
            float a = 0.f, bsum = 0.f;
            for (int u = 0; u < H; ++u) {
                float wv = W_ih[k * H + u];
                a    += wv * W1[u];
                bsum += wv * b1[u];
            }
            su[s] = a;
            sv[s] = bsum + b_ih[k] + b_hh[k];
        }
        uvz[p * 8 + 2 * g]     = pk(su[0], su[1]);
        uvz[p * 8 + 2 * g + 1] = pk(sv[0], sv[1]);
    }
    if (tid < 10) w2q[tid] = pk(W2[2 * tid], W2[2 * tid + 1]);
    if (tid == 0) b2_s = b2[0];
    for (int i = tid; i < 2 * 10 * CTA_ROWS * 2; i += NTHR)
        (&h_s[0][0][0][0])[i] = 0.f;
    __syncthreads();

    // hoist loop-invariant input-path coefficient pairs into registers
    const u64 u_i = uvz[up * 8 + 0], v_i = uvz[up * 8 + 1];
    const u64 u_f = uvz[up * 8 + 2], v_f = uvz[up * 8 + 3];
    const u64 u_g = uvz[up * 8 + 4], v_g = uvz[up * 8 + 5];
    const u64 u_o = uvz[up * 8 + 6], v_o = uvz[up * 8 + 7];

    u64 cA = 0ULL, cB = 0ULL;   // cell state (u0,u1) for row A and row B

    // x prefetch pipeline: float2 covers this lane's two rows
    float2 xv = *(const float2*)(g_xT + rowbase + rA);

    for (int t = 0; t < T_DIM; ++t) {
        const int cur = t & 1, nxt = cur ^ 1;

        // prefetch next x (off critical path)
        float2 xnext = xv;
        if (t + 1 < T_DIM)
            xnext = *(const float2*)(g_xT + (size_t)(t + 1) * B_DIM + rowbase + rA);

        // ---- front-batched h preload: 10x LDS.128, conflict-free ----
        // h4[p] = (h_{2p}(rA), h_{2p+1}(rA), h_{2p}(rB), h_{2p+1}(rB))
        float4 h4[10];
#pragma unroll
        for (int p = 0; p < 10; ++p)
            h4[p] = *(const float4*)&h_s[cur][p][rA][0];

        // ---- out[t-1] = W2 . h + b2 : warp 0 reuses h4 registers ----
        if (up == 0 && t > 0) {
            u64 accA = pk(b2_s, 0.f), accB = 0ULL;
#pragma unroll
            for (int p = 0; p < 10; ++p) {
                u64 w2v = w2q[p];
                accA = fma2(w2v, pk(h4[p].x, h4[p].y), accA);
                accB = fma2(w2v, pk(h4[p].z, h4[p].w), accB);
            }
            float a0, a1, bb0, bb1;
            upk(accA, a0, a1); upk(accB, bb0, bb1);
            *(float2*)(g_outT + (size_t)(t - 1) * B_DIM + rowbase + rA) =
                make_float2(a0 + a1, bb0 + bb1 + b2_s);
        }

        // ---- gates for units {2up, 2up+1}, rows A and B ----
        u64 xpA = pk(xv.x, xv.x), xpB = pk(xv.y, xv.y);
        u64 iA = fma2(xpA, u_i, v_i), iB = fma2(xpB, u_i, v_i);
        u64 fA = fma2(xpA, u_f, v_f), fB = fma2(xpB, u_f, v_f);
        u64 gA = fma2(xpA, u_g, v_g), gB = fma2(xpB, u_g, v_g);
        u64 oA = fma2(xpA, u_o, v_o), oB = fma2(xpB, u_o, v_o);

#pragma unroll
        for (int p = 0; p < 10; ++p) {
            float4 f4 = h4[p];
            // source unit u = 2p
            {
                u64 hA = pk(f4.x, f4.x), hB = pk(f4.z, f4.z);
                ulonglong2 wa = *(const ulonglong2*)&c_WP[(2 * p) * 40 + up4];
                ulonglong2 wb = *(const ulonglong2*)&c_WP[(2 * p) * 40 + up4 + 2];
                iA = fma2(wa.x, hA, iA);  iB = fma2(wa.x, hB, iB);
                fA = fma2(wa.y, hA, fA);  fB = fma2(wa.y, hB, fB);
                gA = fma2(wb.x, hA, gA);  gB = fma2(wb.x, hB, gB);
                oA = fma2(wb.y, hA, oA);  oB = fma2(wb.y, hB, oB);
            }
            // source unit u = 2p+1
            {
                u64 hA = pk(f4.y, f4.y), hB = pk(f4.w, f4.w);
                ulonglong2 wa = *(const ulonglong2*)&c_WP[(2 * p + 1) * 40 + up4];
                ulonglong2 wb = *(const ulonglong2*)&c_WP[(2 * p + 1) * 40 + up4 + 2];
                iA = fma2(wa.x, hA, iA);  iB = fma2(wa.x, hB, iB);
                fA = fma2(wa.y, hA, fA);  fB = fma2(wa.y, hB, fB);
                gA = fma2(wb.x, hA, gA);  gB = fma2(wb.x, hB, gB);
                oA = fma2(wb.y, hA, oA);  oB = fma2(wb.y, hB, oB);
            }
        }

        // ---- cell updates in-warp: 4 cells = (u0,u1) x (rowA,rowB) ----
        float i0A, i1A, f0A, f1A, g0A, g1A, o0A, o1A;
        float i0B, i1B, f0B, f1B, g0B, g1B, o0B, o1B;
        upk(iA, i0A, i1A); upk(fA, f0A, f1A); upk(gA, g0A, g1A); upk(oA, o0A, o1A);
        upk(iB, i0B, i1B); upk(fB, f0B, f1B); upk(gB, g0B, g1B); upk(oB, o0B, o1B);
        float c0A, c1A, c0B, c1B;
        upk(cA, c0A, c1A); upk(cB, c0B, c1B);
        float h0A, h1A, h0B, h1B;
        cell(i0A, f0A, g0A, o0A, c0A, h0A);
        cell(i1A, f1A, g1A, o1A, c1A, h1A);
        cell(i0B, f0B, g0B, o0B, c0B, h0B);
        cell(i1B, f1B, g1B, o1B, c1B, h1B);
        cA = pk(c0A, c1A); cB = pk(c0B, c1B);

        // publish h: one STS.128 = (u0 rA, u1 rA, u0 rB, u1 rB)
        *(float4*)&h_s[nxt][up][rA][0] = make_float4(h0A, h1A, h0B, h1B);

        // ---- single barrier: publish h, protect buffer swap ----
        __syncthreads();

        xv = xnext;
    }

    // final output row: out[T-1] from buffer (T_DIM & 1)
    if (up == 0) {
        const int cur = T_DIM & 1;
        u64 accA = 0ULL, accB = 0ULL;
#pragma unroll
        for (int p = 0; p < 10; ++p) {
            float4 f4 = *(const float4*)&h_s[cur][p][rA][0];
            u64 w2v = w2q[p];
            accA = fma2(w2v, pk(f4.x, f4.y), accA);
            accB = fma2(w2v, pk(f4.z, f4.w), accB);
        }
        float a0, a1, bb0, bb1;
        upk(accA, a0, a1); upk(accB, bb0, bb1);
        *(float2*)(g_outT + (size_t)(T_DIM - 1) * B_DIM + rowbase + rA) =
            make_float2(a0 + a1 + b2_s, bb0 + bb1 + b2_s);
    }
}

// ---------------- launcher ----------------
extern "C" void kernel_launch(void* const* d_in, const int* in_sizes, int n_in,
                              void* d_out, int out_size)
{
    const float* x    = (const float*)d_in[0];
    const float* W1   = (const float*)d_in[1];
    const float* b1   = (const float*)d_in[2];
    const float* W_ih = (const float*)d_in[3];
    const float* W_hh = (const float*)d_in[4];
    const float* b_ih = (const float*)d_in[5];
    const float* b_hh = (const float*)d_in[6];
    const float* W2   = (const float*)d_in[7];
    const float* b2   = (const float*)d_in[8];
    float* out = (float*)d_out;

    (void)in_sizes; (void)n_in; (void)out_size;

    // pack recurrent weights, then copy staging -> constant bank.
    // NOTE round-6 bug fix: g_wpack is a __device__ symbol; its host-side
    // token is NOT a device pointer. Resolve the real address first.
    pack_weights<<<4, 256>>>(W_hh);
    void* wsrc = nullptr;
    cudaGetSymbolAddress(&wsrc, g_wpack);
    cudaMemcpyToSymbolAsync(c_WP, wsrc, sizeof(u64) * H * 40, 0,
                            cudaMemcpyDeviceToDevice, 0);

    // x[B][T] -> g_xT[T][B]
    transpose_in<<<dim3(T_DIM / 32, B_DIM / 32), dim3(32, 8)>>>(x);

    // recurrent scan: 128 CTAs x 320 threads, const-mem weights
    lstm_kernel<<<B_DIM / CTA_ROWS, NTHR>>>(W1, b1, W_ih, W_hh, b_ih, b_hh, W2, b2);

    // g_outT[T][B] -> out[B][T]
    transpose_out<<<dim3(B_DIM / 32, T_DIM / 32), dim3(32, 8)>>>(out);
}

// round 8
// speedup vs baseline: 1.3207x; 1.3207x over previous
#include <cuda_runtime.h>

// Problem dims (fixed by reference setup_inputs)
#define B_DIM 8192
#define T_DIM 2048
#define H     20
#define CTA_ROWS 64       // batch rows per CTA (two independent 32-row groups)
#define NTHR  320         // 10 warps = 2 groups x 5 warps

typedef unsigned long long u64;

// Scratch (allocation-free rule: __device__ globals)
__device__ float g_xT[(size_t)T_DIM * B_DIM];   // x transposed: [t][b]
__device__ float g_outT[(size_t)T_DIM * B_DIM]; // out transposed: [t][b]

// ---------------- f32x2 helpers ----------------
__device__ __forceinline__ u64 pk(float lo, float hi) {
    u64 r; asm("mov.b64 %0,{%1,%2};" : "=l"(r) : "f"(lo), "f"(hi)); return r;
}
__device__ __forceinline__ void upk(u64 v, float& lo, float& hi) {
    asm("mov.b64 {%0,%1},%2;" : "=f"(lo), "=f"(hi) : "l"(v));
}
__device__ __forceinline__ u64 fma2(u64 a, u64 b, u64 c) {
    u64 d; asm("fma.rn.f32x2 %0,%1,%2,%3;" : "=l"(d) : "l"(a), "l"(b), "l"(c)); return d;
}
__device__ __forceinline__ float tanh_a(float x) {
    float r; asm("tanh.approx.f32 %0,%1;" : "=f"(r) : "f"(x)); return r;
}

// LSTM cell via MUFU.TANH: 5 MUFU + ~9 FMA-pipe ops.
// sigmoid(x) = 0.5*tanh(0.5x) + 0.5
__device__ __forceinline__ void cell(float ig, float fg, float gg, float og,
                                     float& c, float& h) {
    float si = fmaf(0.5f, tanh_a(0.5f * ig), 0.5f);
    float sf = fmaf(0.5f, tanh_a(0.5f * fg), 0.5f);
    float so = fmaf(0.5f, tanh_a(0.5f * og), 0.5f);
    float tg = tanh_a(gg);
    float cn = sf * c + si * tg;
    float tc = tanh_a(cn);
    c = cn;
    h = so * tc;
}

// ---------------- transposes ----------------
__global__ void transpose_in(const float* __restrict__ in) {
    __shared__ float tile[32][33];
    int c0 = blockIdx.x * 32, r0 = blockIdx.y * 32;
    int tx = threadIdx.x, ty = threadIdx.y;
#pragma unroll
    for (int i = 0; i < 32; i += 8)
        tile[ty + i][tx] = in[(size_t)(r0 + ty + i) * T_DIM + c0 + tx];
    __syncthreads();
#pragma unroll
    for (int i = 0; i < 32; i += 8)
        g_xT[(size_t)(c0 + ty + i) * B_DIM + r0 + tx] = tile[tx][ty + i];
}

__global__ void transpose_out(float* __restrict__ out) {
    __shared__ float tile[32][33];
    int c0 = blockIdx.x * 32, r0 = blockIdx.y * 32;
    int tx = threadIdx.x, ty = threadIdx.y;
#pragma unroll
    for (int i = 0; i < 32; i += 8)
        tile[ty + i][tx] = g_outT[(size_t)(r0 + ty + i) * B_DIM + c0 + tx];
    __syncthreads();
#pragma unroll
    for (int i = 0; i < 32; i += 8)
        out[(size_t)(c0 + ty + i) * T_DIM + r0 + tx] = tile[tx][ty + i];
}

// ---------------- main persistent LSTM kernel ----------------
// 128 CTAs x 320 threads. CTA = TWO independent 32-row LSTM groups.
// Group g (warps 5g..5g+4) owns rows [g*32, g*32+32); lane = row in group.
// Warp-in-group wg owns dest units {4wg..4wg+3} (16 gate rows), all 32 rows.
// Each group syncs ONLY itself via named barrier (1+g) -> groups drift out of
// phase, overlapping LDS/FMA/MUFU bursts across groups. Weight/uv tables are
// read-only shared. h double-buffered per group.
__global__ __launch_bounds__(NTHR, 1) void lstm_kernel(
    const float* __restrict__ W1, const float* __restrict__ b1,
    const float* __restrict__ W_ih, const float* __restrict__ W_hh,
    const float* __restrict__ b_ih, const float* __restrict__ b_hh,
    const float* __restrict__ W2, const float* __restrict__ b2)
{
    // Wg_s[u][wg*8 + g*2 + s] = (W_hh[g*H + 4wg+2s][u], W_hh[g*H + 4wg+2s+1][u])
    __shared__ __align__(16) u64 Wg_s[H][40];        // 6.4 KB
    __shared__ __align__(16) u64 uvu_s[40], uvv_s[40];
    __shared__ u64 w2q[10];                          // (W2[2p], W2[2p+1])
    __shared__ float b2_s;
    // h[buf][group][row][unit]; row padded to 28 floats (112B) => LDS.128
    // phases hit distinct banks (28*r mod 32 cycles through 8 offsets).
    __shared__ __align__(16) float hbuf[2][2][32][28];   // 28.7 KB total smem

    const int tid   = threadIdx.x;
    const int lane  = tid & 31;
    const int wid   = tid >> 5;
    const int group = wid / 5;                       // 0: warps 0-4, 1: warps 5-9
    const int wg    = wid - 5 * group;               // warp-in-group 0..4
    const int grow  = blockIdx.x * CTA_ROWS + group * 32 + lane; // global row
    const int bid   = 1 + group;                     // named barrier id

    // --- one-time setup ---
    for (int i = tid; i < H * 40; i += NTHR) {
        int u = i / 40, j = i % 40;
        int w_ = j >> 3, jj = j & 7, g = jj >> 1, s = jj & 1;
        int ua = 4 * w_ + 2 * s;
        Wg_s[u][j] = pk(W_hh[(g * H + ua) * H + u],
                        W_hh[(g * H + ua + 1) * H + u]);
    }
    if (tid < 40) {
        int w_ = tid >> 3, jj = tid & 7, g = jj >> 1, s = jj & 1;
        int ua = 4 * w_ + 2 * s;
        float su[2], sv[2];
#pragma unroll
        for (int q = 0; q < 2; ++q) {
            int k = g * H + ua + q;
            float a = 0.f, bsum = 0.f;
            for (int u = 0; u < H; ++u) {
                float wv = W_ih[k * H + u];
                a    += wv * W1[u];
                bsum += wv * b1[u];
            }
            su[q] = a;
            sv[q] = bsum + b_ih[k] + b_hh[k];
        }
        uvu_s[tid] = pk(su[0], su[1]);
        uvv_s[tid] = pk(sv[0], sv[1]);
    }
    if (tid < 10) w2q[tid] = pk(W2[2 * tid], W2[2 * tid + 1]);
    if (tid == 0) b2_s = b2[0];
    for (int i = tid; i < 2 * 2 * 32 * 28; i += NTHR)
        (&hbuf[0][0][0][0])[i] = 0.f;
    __syncthreads();

    // hoist input-path coefficients (8 gate-pairs) into registers
    u64 uu[8], vv[8];
#pragma unroll
    for (int j = 0; j < 8; ++j) {
        uu[j] = uvu_s[wg * 8 + j];
        vv[j] = uvv_s[wg * 8 + j];
    }

    float cst[4] = {0.f, 0.f, 0.f, 0.f};             // c for units 4wg..4wg+3

    float xv = g_xT[grow];                           // x prefetch

    for (int t = 0; t < T_DIM; ++t) {
        const int cur = t & 1, nxt = cur ^ 1;

        float xn = xv;
        if (t + 1 < T_DIM)
            xn = g_xT[(size_t)(t + 1) * B_DIM + grow];

        // ---- load full h vector for this row: 5x LDS.128, conflict-free ----
        float4 h4[5];
#pragma unroll
        for (int j = 0; j < 5; ++j)
            h4[j] = *(const float4*)&hbuf[cur][group][lane][4 * j];
        float hv[20];
#pragma unroll
        for (int j = 0; j < 5; ++j) {
            hv[4 * j + 0] = h4[j].x; hv[4 * j + 1] = h4[j].y;
            hv[4 * j + 2] = h4[j].z; hv[4 * j + 3] = h4[j].w;
        }

        // ---- out[t-1] = W2 . h + b2 : group's warp 0 reuses loaded h ----
        if (wg == 0 && t > 0) {
            u64 oa = 0ULL;
#pragma unroll
            for (int j = 0; j < 5; ++j) {
                oa = fma2(w2q[2 * j],     pk(h4[j].x, h4[j].y), oa);
                oa = fma2(w2q[2 * j + 1], pk(h4[j].z, h4[j].w), oa);
            }
            float lo, hi; upk(oa, lo, hi);
            g_outT[(size_t)(t - 1) * B_DIM + grow] = lo + hi + b2_s;
        }

        // ---- 16 gate rows for units {4wg..4wg+3}, this row ----
        u64 x2 = pk(xv, xv);
        u64 acc[8];
#pragma unroll
        for (int j = 0; j < 8; ++j)
            acc[j] = fma2(x2, uu[j], vv[j]);

#pragma unroll
        for (int u = 0; u < H; ++u) {
            u64 hp = pk(hv[u], hv[u]);
            ulonglong2 A = *(const ulonglong2*)&Wg_s[u][wg * 8];
            ulonglong2 Bq = *(const ulonglong2*)&Wg_s[u][wg * 8 + 2];
            ulonglong2 C = *(const ulonglong2*)&Wg_s[u][wg * 8 + 4];
            ulonglong2 D = *(const ulonglong2*)&Wg_s[u][wg * 8 + 6];
            acc[0] = fma2(A.x,  hp, acc[0]);  acc[1] = fma2(A.y,  hp, acc[1]);
            acc[2] = fma2(Bq.x, hp, acc[2]);  acc[3] = fma2(Bq.y, hp, acc[3]);
            acc[4] = fma2(C.x,  hp, acc[4]);  acc[5] = fma2(C.y,  hp, acc[5]);
            acc[6] = fma2(D.x,  hp, acc[6]);  acc[7] = fma2(D.y,  hp, acc[7]);
        }

        // ---- cell updates: unit m = 4wg+m, m=0..3 ----
        // gate g of unit m lives in acc[g*2 + (m>>1)], half (m&1)
        float hn[4];
#pragma unroll
        for (int m = 0; m < 4; ++m) {
            float ig0, ig1, fg0, fg1, gg0, gg1, og0, og1;
            upk(acc[0 + (m >> 1)], ig0, ig1);
            upk(acc[2 + (m >> 1)], fg0, fg1);
            upk(acc[4 + (m >> 1)], gg0, gg1);
            upk(acc[6 + (m >> 1)], og0, og1);
            float ig = (m & 1) ? ig1 : ig0;
            float fg = (m & 1) ? fg1 : fg0;
            float gg = (m & 1) ? gg1 : gg0;
            float og = (m & 1) ? og1 : og0;
            cell(ig, fg, gg, og, cst[m], hn[m]);
        }

        // publish h for units 4wg..4wg+3, this row: one STS.128
        *(float4*)&hbuf[nxt][group][lane][4 * wg] =
            make_float4(hn[0], hn[1], hn[2], hn[3]);

        // ---- group-local barrier only: groups drift independently ----
        asm volatile("bar.sync %0, %1;" :: "r"(bid), "r"(160) : "memory");

        xv = xn;
    }

    // final output row: out[T-1] from buffer (T_DIM & 1)
    if (wg == 0) {
        const int cur = T_DIM & 1;
        u64 oa = 0ULL;
#pragma unroll
        for (int j = 0; j < 5; ++j) {
            float4 f4 = *(const float4*)&hbuf[cur][group][lane][4 * j];
            oa = fma2(w2q[2 * j],     pk(f4.x, f4.y), oa);
            oa = fma2(w2q[2 * j + 1], pk(f4.z, f4.w), oa);
        }
        float lo, hi; upk(oa, lo, hi);
        g_outT[(size_t)(T_DIM - 1) * B_DIM + grow] = lo + hi + b2_s;
    }
}

// ---------------- launcher ----------------
extern "C" void kernel_launch(void* const* d_in, const int* in_sizes, int n_in,
                              void* d_out, int out_size)
{
    const float* x    = (const float*)d_in[0];
    const float* W1   = (const float*)d_in[1];
    const float* b1   = (const float*)d_in[2];
    const float* W_ih = (const float*)d_in[3];
    const float* W_hh = (const float*)d_in[4];
    const float* b_ih = (const float*)d_in[5];
    const float* b_hh = (const float*)d_in[6];
    const float* W2   = (const float*)d_in[7];
    const float* b2   = (const float*)d_in[8];
    float* out = (float*)d_out;

    (void)in_sizes; (void)n_in; (void)out_size;

    // x[B][T] -> g_xT[T][B]
    transpose_in<<<dim3(T_DIM / 32, B_DIM / 32), dim3(32, 8)>>>(x);

    // recurrent scan: 128 CTAs x 320 threads, two drifting 32-row groups/CTA
    lstm_kernel<<<B_DIM / CTA_ROWS, NTHR>>>(W1, b1, W_ih, W_hh, b_ih, b_hh, W2, b2);

    // g_outT[T][B] -> out[B][T]
    transpose_out<<<dim3(B_DIM / 32, T_DIM / 32), dim3(32, 8)>>>(out);
}

// round 9
// speedup vs baseline: 1.5353x; 1.1625x over previous
#include <cuda_runtime.h>

// Problem dims (fixed by reference setup_inputs)
#define B_DIM 8192
#define T_DIM 2048
#define H     20
#define CTA_ROWS 64       // batch rows per CTA
#define NTHR  320         // 10 warps; warp w = unit-pair w; lane carries 2 rows
#define UPIN  10          // source units whose weights are pinned in registers

typedef unsigned long long u64;

// Scratch (allocation-free rule: __device__ globals)
__device__ float g_xT[(size_t)T_DIM * B_DIM];   // x transposed: [t][b]
__device__ float g_outT[(size_t)T_DIM * B_DIM]; // out transposed: [t][b]

// ---------------- f32x2 helpers ----------------
__device__ __forceinline__ u64 pk(float lo, float hi) {
    u64 r; asm("mov.b64 %0,{%1,%2};" : "=l"(r) : "f"(lo), "f"(hi)); return r;
}
__device__ __forceinline__ void upk(u64 v, float& lo, float& hi) {
    asm("mov.b64 {%0,%1},%2;" : "=f"(lo), "=f"(hi) : "l"(v));
}
__device__ __forceinline__ u64 fma2(u64 a, u64 b, u64 c) {
    u64 d; asm("fma.rn.f32x2 %0,%1,%2,%3;" : "=l"(d) : "l"(a), "l"(b), "l"(c)); return d;
}
__device__ __forceinline__ float tanh_a(float x) {
    float r; asm("tanh.approx.f32 %0,%1;" : "=f"(r) : "f"(x)); return r;
}

// LSTM cell via MUFU.TANH: 5 MUFU + ~9 FMA-pipe ops.
// sigmoid(x) = 0.5*tanh(0.5x) + 0.5
__device__ __forceinline__ void cell(float ig, float fg, float gg, float og,
                                     float& c, float& h) {
    float si = fmaf(0.5f, tanh_a(0.5f * ig), 0.5f);
    float sf = fmaf(0.5f, tanh_a(0.5f * fg), 0.5f);
    float so = fmaf(0.5f, tanh_a(0.5f * og), 0.5f);
    float tg = tanh_a(gg);
    float cn = sf * c + si * tg;
    float tc = tanh_a(cn);
    c = cn;
    h = so * tc;
}

// ---------------- transposes ----------------
__global__ void transpose_in(const float* __restrict__ in) {
    __shared__ float tile[32][33];
    int c0 = blockIdx.x * 32, r0 = blockIdx.y * 32;
    int tx = threadIdx.x, ty = threadIdx.y;
#pragma unroll
    for (int i = 0; i < 32; i += 8)
        tile[ty + i][tx] = in[(size_t)(r0 + ty + i) * T_DIM + c0 + tx];
    __syncthreads();
#pragma unroll
    for (int i = 0; i < 32; i += 8)
        g_xT[(size_t)(c0 + ty + i) * B_DIM + r0 + tx] = tile[tx][ty + i];
}

__global__ void transpose_out(float* __restrict__ out) {
    __shared__ float tile[32][33];
    int c0 = blockIdx.x * 32, r0 = blockIdx.y * 32;
    int tx = threadIdx.x, ty = threadIdx.y;
#pragma unroll
    for (int i = 0; i < 32; i += 8)
        tile[ty + i][tx] = g_outT[(size_t)(r0 + ty + i) * B_DIM + c0 + tx];
    __syncthreads();
#pragma unroll
    for (int i = 0; i < 32; i += 8)
        out[(size_t)(c0 + ty + i) * T_DIM + r0 + tx] = tile[tx][ty + i];
}

// ---------------- main persistent LSTM kernel ----------------
// 128 CTAs x 320 threads (10 warps). CTA owns 64 batch rows.
// Warp up owns UNIT PAIR {2up, 2up+1}. Lane owns rows {2*lane, 2*lane+1}.
// f32x2 packs (unit a, unit b) of the same gate; two accumulator sets (row A/B).
// Weights for source units [0, UPIN) are PINNED IN REGISTERS (loaded once);
// the remainder streams from smem. Cuts crossbar weight traffic in half and
// removes the post-barrier LDS dependency for the first UPIN iterations
// (ptxas cannot hoist LDS across BAR — registers sidestep that).
// One __syncthreads per timestep (double-buffered h).
__global__ __launch_bounds__(NTHR, 1) void lstm_kernel(
    const float* __restrict__ W1, const float* __restrict__ b1,
    const float* __restrict__ W_ih, const float* __restrict__ W_hh,
    const float* __restrict__ b_ih, const float* __restrict__ b_hh,
    const float* __restrict__ W2, const float* __restrict__ b2)
{
    // WP_s[u][up*4 + g] = (W_hh[g*H+2up][u], W_hh[g*H+2up+1][u])
    __shared__ __align__(16) u64 WP_s[H][40];        // 6.4 KB
    __shared__ __align__(16) u64 uvz[80];            // [p*8+2g]=u-pair, [+1]=v-pair
    __shared__ u64 w2p[H];                           // (W2[u], W2[u]) duplicated
    __shared__ float b2_s;
    __shared__ __align__(8) float h_s[2][H][CTA_ROWS]; // [buf][u][row]

    const int tid  = threadIdx.x;
    const int lane = tid & 31;
    const int up   = tid >> 5;                       // unit pair index 0..9
    const int up4  = up * 4;
    const int rowbase = blockIdx.x * CTA_ROWS;
    const int rA = 2 * lane;                         // rows owned by this lane

    // --- one-time setup ---
    for (int i = tid; i < H * 40; i += NTHR) {
        int u = i / 40, j = i % 40;
        int p = j >> 2, g = j & 3;                   // unit pair p, gate g
        float wa = W_hh[(g * H + 2 * p    ) * H + u];
        float wb = W_hh[(g * H + 2 * p + 1) * H + u];
        WP_s[u][j] = pk(wa, wb);
    }
    if (tid < 40) {
        int p = tid >> 2, g = tid & 3;
        float su[2], sv[2];
#pragma unroll
        for (int s = 0; s < 2; ++s) {
            int k = g * H + 2 * p + s;               // original gate-row index
            float a = 0.f, bsum = 0.f;
            for (int u = 0; u < H; ++u) {
                float wv = W_ih[k * H + u];
                a    += wv * W1[u];
                bsum += wv * b1[u];
            }
            su[s] = a;
            sv[s] = bsum + b_ih[k] + b_hh[k];
        }
        uvz[p * 8 + 2 * g]     = pk(su[0], su[1]);
        uvz[p * 8 + 2 * g + 1] = pk(sv[0], sv[1]);
    }
    if (tid < H) { float wv = W2[tid]; w2p[tid] = pk(wv, wv); }
    if (tid == 0) b2_s = b2[0];
    for (int i = tid; i < 2 * H * CTA_ROWS; i += NTHR) h_s[0][0][i] = 0.f;
    __syncthreads();

    // hoist loop-invariant input-path coefficient pairs into registers
    const u64 u_i = uvz[up * 8 + 0], v_i = uvz[up * 8 + 1];
    const u64 u_f = uvz[up * 8 + 2], v_f = uvz[up * 8 + 3];
    const u64 u_g = uvz[up * 8 + 4], v_g = uvz[up * 8 + 5];
    const u64 u_o = uvz[up * 8 + 6], v_o = uvz[up * 8 + 7];

    // PIN weights for source units [0, UPIN): 4 u64 per unit = 80 registers
    ulonglong2 wpa[UPIN], wpb[UPIN];
#pragma unroll
    for (int u = 0; u < UPIN; ++u) {
        wpa[u] = *(const ulonglong2*)&WP_s[u][up4];       // (w_i, w_f) pairs
        wpb[u] = *(const ulonglong2*)&WP_s[u][up4 + 2];   // (w_g, w_o) pairs
    }

    u64 cA = 0ULL, cB = 0ULL;   // cell state (u0,u1) for row A and row B

    // x prefetch pipeline: float2 covers this lane's two rows
    float2 xv = *(const float2*)(g_xT + rowbase + rA);

    for (int t = 0; t < T_DIM; ++t) {
        const int cur = t & 1, nxt = cur ^ 1;

        // prefetch next x (off critical path)
        float2 xnext = xv;
        if (t + 1 < T_DIM)
            xnext = *(const float2*)(g_xT + (size_t)(t + 1) * B_DIM + rowbase + rA);

        // ---- preload full h vector for both rows (raw (hA,hB) pairs) ----
        u64 h2[H];
#pragma unroll
        for (int u = 0; u < H; ++u)
            h2[u] = *(const u64*)&h_s[cur][u][rA];   // LDS.64, conflict-free

        // ---- out[t-1] = W2 . h + b2 : warp 0 reuses its h2 registers ----
        if (up == 0 && t > 0) {
            u64 oacc = pk(b2_s, b2_s);
#pragma unroll
            for (int u = 0; u < H; ++u)
                oacc = fma2(w2p[u], h2[u], oacc);    // (outA, outB)
            float o0, o1; upk(oacc, o0, o1);
            *(float2*)(g_outT + (size_t)(t - 1) * B_DIM + rowbase + rA) =
                make_float2(o0, o1);
        }

        // ---- gates for units {2up, 2up+1}, rows A and B ----
        u64 xpA = pk(xv.x, xv.x), xpB = pk(xv.y, xv.y);
        u64 iA = fma2(xpA, u_i, v_i), iB = fma2(xpB, u_i, v_i);
        u64 fA = fma2(xpA, u_f, v_f), fB = fma2(xpB, u_f, v_f);
        u64 gA = fma2(xpA, u_g, v_g), gB = fma2(xpB, u_g, v_g);
        u64 oA = fma2(xpA, u_o, v_o), oB = fma2(xpB, u_o, v_o);

        // pinned-weight iterations: register operands, no LDS on critical path
#pragma unroll
        for (int u = 0; u < UPIN; ++u) {
            float hA, hB; upk(h2[u], hA, hB);
            u64 hpA = pk(hA, hA), hpB = pk(hB, hB);
            iA = fma2(wpa[u].x, hpA, iA);  iB = fma2(wpa[u].x, hpB, iB);
            fA = fma2(wpa[u].y, hpA, fA);  fB = fma2(wpa[u].y, hpB, fB);
            gA = fma2(wpb[u].x, hpA, gA);  gB = fma2(wpb[u].x, hpB, gB);
            oA = fma2(wpb[u].y, hpA, oA);  oB = fma2(wpb[u].y, hpB, oB);
        }
        // streamed-weight iterations
#pragma unroll
        for (int u = UPIN; u < H; ++u) {
            float hA, hB; upk(h2[u], hA, hB);
            u64 hpA = pk(hA, hA), hpB = pk(hB, hB);
            ulonglong2 wa = *(const ulonglong2*)&WP_s[u][up4];      // (w_i, w_f)
            ulonglong2 wb = *(const ulonglong2*)&WP_s[u][up4 + 2];  // (w_g, w_o)
            iA = fma2(wa.x, hpA, iA);  iB = fma2(wa.x, hpB, iB);
            fA = fma2(wa.y, hpA, fA);  fB = fma2(wa.y, hpB, fB);
            gA = fma2(wb.x, hpA, gA);  gB = fma2(wb.x, hpB, gB);
            oA = fma2(wb.y, hpA, oA);  oB = fma2(wb.y, hpB, oB);
        }

        // ---- cell updates in-warp: 4 cells = (u0,u1) x (rowA,rowB) ----
        float i0A, i1A, f0A, f1A, g0A, g1A, o0A, o1A;
        float i0B, i1B, f0B, f1B, g0B, g1B, o0B, o1B;
        upk(iA, i0A, i1A); upk(fA, f0A, f1A); upk(gA, g0A, g1A); upk(oA, o0A, o1A);
        upk(iB, i0B, i1B); upk(fB, f0B, f1B); upk(gB, g0B, g1B); upk(oB, o0B, o1B);
        float c0A, c1A, c0B, c1B;
        upk(cA, c0A, c1A); upk(cB, c0B, c1B);
        float h0A, h1A, h0B, h1B;
        cell(i0A, f0A, g0A, o0A, c0A, h0A);
        cell(i1A, f1A, g1A, o1A, c1A, h1A);
        cell(i0B, f0B, g0B, o0B, c0B, h0B);
        cell(i1B, f1B, g1B, o1B, c1B, h1B);
        cA = pk(c0A, c1A); cB = pk(c0B, c1B);

        // publish h: unit 2up gets (h0A at rA, h0B at rA+1); unit 2up+1 likewise
        *(u64*)&h_s[nxt][2 * up    ][rA] = pk(h0A, h0B);   // STS.64
        *(u64*)&h_s[nxt][2 * up + 1][rA] = pk(h1A, h1B);

        // ---- single barrier: publish h, protect buffer swap ----
        __syncthreads();

        xv = xnext;
    }

    // final output row: out[T-1] from buffer (T_DIM & 1)
    if (up == 0) {
        const int cur = T_DIM & 1;
        u64 oacc = pk(b2_s, b2_s);
#pragma unroll
        for (int u = 0; u < H; ++u)
            oacc = fma2(w2p[u], *(const u64*)&h_s[cur][u][rA], oacc);
        float o0, o1; upk(oacc, o0, o1);
        *(float2*)(g_outT + (size_t)(T_DIM - 1) * B_DIM + rowbase + rA) =
            make_float2(o0, o1);
    }
}

// ---------------- launcher ----------------
extern "C" void kernel_launch(void* const* d_in, const int* in_sizes, int n_in,
                              void* d_out, int out_size)
{
    const float* x    = (const float*)d_in[0];
    const float* W1   = (const float*)d_in[1];
    const float* b1   = (const float*)d_in[2];
    const float* W_ih = (const float*)d_in[3];
    const float* W_hh = (const float*)d_in[4];
    const float* b_ih = (const float*)d_in[5];
    const float* b_hh = (const float*)d_in[6];
    const float* W2   = (const float*)d_in[7];
    const float* b2   = (const float*)d_in[8];
    float* out = (float*)d_out;

    (void)in_sizes; (void)n_in; (void)out_size;

    // x[B][T] -> g_xT[T][B]
    transpose_in<<<dim3(T_DIM / 32, B_DIM / 32), dim3(32, 8)>>>(x);

    // recurrent scan: 128 CTAs x 320 threads, half the weights register-pinned
    lstm_kernel<<<B_DIM / CTA_ROWS, NTHR>>>(W1, b1, W_ih, W_hh, b_ih, b_hh, W2, b2);

    // g_outT[T][B] -> out[B][T]
    transpose_out<<<dim3(B_DIM / 32, T_DIM / 32), dim3(32, 8)>>>(out);
}